// round 15
// baseline (speedup 1.0000x reference)
#include <cuda_runtime.h>
#include <cuda_fp16.h>
#include <cstdint>

#define N_NODES 100000
#define N_EDGES 3200000
#define N_GRAPHS 1024
#define HID 64

#define SCAN_BLOCKS 98   // ceil(100000 / 1024)
#define WARP_TILES 6250  // 100000 / 16 (exact)

// ---------------------------------------------------------------------------
// Scratch (device globals; no allocations allowed).
// INVARIANT: g_deg and g_gsum are zero at the start of every kernel_launch
// (zero-initialized at module load; re-zeroed by scatter/head at the end of
// each launch sequence).
// ---------------------------------------------------------------------------
__device__ int     g_deg[N_NODES + 4];
__device__ int     g_off[N_NODES + 1];
__device__ int     g_pos[N_NODES];           // scatter cursors (seeded by scanC)
__device__ int     g_srcs[N_EDGES];
__device__ int     g_bsum[SCAN_BLOCKS];
__device__ uint4   g_xh[N_NODES];            // x padded to 8 halfs
__device__ float   g_z1[N_NODES * 5 + 12];
__device__ uint4   g_h1v[N_NODES * 8];       // layer-1 output, fp16 [N][64]
__device__ uint4   g_z2v[N_NODES * 8];       // h1 + agg2, fp16 [N][64]
__device__ float   g_gsum[N_GRAPHS * HID];

// ---------------------------------------------------------------------------
// Fused prep + degree histogram.
// Threads [0, N_EDGES/8): 8 edges each, RED into g_deg (zero on entry).
// Threads [0, N_NODES): also pack x into fp16 rows.
// Grid covers N_EDGES/8 = 400000 threads.
// ---------------------------------------------------------------------------
__global__ void prep_hist_kernel(const float* __restrict__ x,
                                 const int* __restrict__ ei) {
    int t = blockIdx.x * blockDim.x + threadIdx.x;
    if (t < N_NODES) {
        const float* xs = x + t * 5;
        __half2 h0 = __floats2half2_rn(xs[0], xs[1]);
        __half2 h1 = __floats2half2_rn(xs[2], xs[3]);
        __half2 h2 = __floats2half2_rn(xs[4], 0.0f);
        __half2 h3 = __floats2half2_rn(0.0f, 0.0f);
        uint4 v;
        v.x = *(unsigned*)&h0; v.y = *(unsigned*)&h1;
        v.z = *(unsigned*)&h2; v.w = *(unsigned*)&h3;
        g_xh[t] = v;
    }
    if (t >= N_EDGES / 8) return;
    const int4* dp = (const int4*)(ei + N_EDGES);
    int4 a = dp[2 * t], b = dp[2 * t + 1];
    atomicAdd(&g_deg[a.x], 1);
    atomicAdd(&g_deg[a.y], 1);
    atomicAdd(&g_deg[a.z], 1);
    atomicAdd(&g_deg[a.w], 1);
    atomicAdd(&g_deg[b.x], 1);
    atomicAdd(&g_deg[b.y], 1);
    atomicAdd(&g_deg[b.z], 1);
    atomicAdd(&g_deg[b.w], 1);
}

// ---------------------------------------------------------------------------
// Scan phase A: per-block sums (1024 nodes/block).
// ---------------------------------------------------------------------------
__global__ void scanA_kernel() {
    __shared__ int wsum[8];
    int t = threadIdx.x;
    int n0 = blockIdx.x * 1024 + t * 4;
    int s = 0;
    if (n0 + 3 < N_NODES) {
        int4 v = *(const int4*)&g_deg[n0];
        s = v.x + v.y + v.z + v.w;
    } else {
#pragma unroll
        for (int i = 0; i < 4; ++i)
            if (n0 + i < N_NODES) s += g_deg[n0 + i];
    }
    int lane = t & 31;
#pragma unroll
    for (int off = 16; off; off >>= 1) s += __shfl_xor_sync(0xffffffffu, s, off);
    if (lane == 0) wsum[t >> 5] = s;
    __syncthreads();
    if (t < 8) {
        int v = wsum[t];
#pragma unroll
        for (int off = 4; off; off >>= 1) v += __shfl_xor_sync(0xffu, v, off);
        if (t == 0) g_bsum[blockIdx.x] = v;
    }
}

// ---------------------------------------------------------------------------
// Scan phase C (with inlined phase B); writes g_off AND g_pos cursors.
// ---------------------------------------------------------------------------
__global__ void scanC_kernel() {
    __shared__ int sbs[128];
    __shared__ int ssum[256];
    int t = threadIdx.x;
    if (t < 128) sbs[t] = (t < SCAN_BLOCKS) ? g_bsum[t] : 0;
    __syncthreads();
    for (int d = 1; d < 128; d <<= 1) {
        int u = (t >= d && t < 128) ? sbs[t - d] : 0;
        __syncthreads();
        if (t < 128) sbs[t] += u;
        __syncthreads();
    }
    int boff = (blockIdx.x == 0) ? 0 : sbs[blockIdx.x - 1];
    if (blockIdx.x == 0 && t == 0) g_off[N_NODES] = sbs[SCAN_BLOCKS - 1];

    int n0 = blockIdx.x * 1024 + t * 4;
    int v0 = 0, v1 = 0, v2 = 0, v3 = 0;
    if (n0 + 3 < N_NODES) {
        int4 v = *(const int4*)&g_deg[n0];
        v0 = v.x; v1 = v.y; v2 = v.z; v3 = v.w;
    } else {
        if (n0 + 0 < N_NODES) v0 = g_deg[n0 + 0];
        if (n0 + 1 < N_NODES) v1 = g_deg[n0 + 1];
        if (n0 + 2 < N_NODES) v2 = g_deg[n0 + 2];
        if (n0 + 3 < N_NODES) v3 = g_deg[n0 + 3];
    }
    int s = v0 + v1 + v2 + v3;
    ssum[t] = s;
    __syncthreads();
    for (int d = 1; d < 256; d <<= 1) {
        int u = (t >= d) ? ssum[t - d] : 0;
        __syncthreads();
        ssum[t] += u;
        __syncthreads();
    }
    int prefix = boff + ssum[t] - s;
    if (n0 + 0 < N_NODES) { g_off[n0 + 0] = prefix; g_pos[n0 + 0] = prefix; prefix += v0; }
    if (n0 + 1 < N_NODES) { g_off[n0 + 1] = prefix; g_pos[n0 + 1] = prefix; prefix += v1; }
    if (n0 + 2 < N_NODES) { g_off[n0 + 2] = prefix; g_pos[n0 + 2] = prefix; prefix += v2; }
    if (n0 + 3 < N_NODES) { g_off[n0 + 3] = prefix; g_pos[n0 + 3] = prefix; }
}

// ---------------------------------------------------------------------------
// Scatter edges into CSR via cursor atomics, 8 edges/thread.
// Also re-zeros g_deg (scanC was the last reader) to restore the invariant.
// ---------------------------------------------------------------------------
__global__ void scatter_kernel(const int* __restrict__ ei) {
    int t = blockIdx.x * blockDim.x + threadIdx.x;
    if (t < N_NODES + 4) g_deg[t] = 0;
    if (t >= N_EDGES / 8) return;
    const int4* sp = (const int4*)ei;
    const int4* dp = (const int4*)(ei + N_EDGES);
    int4 sa = sp[2 * t], sb = sp[2 * t + 1];
    int4 da = dp[2 * t], db = dp[2 * t + 1];
    int p0 = atomicAdd(&g_pos[da.x], 1);
    int p1 = atomicAdd(&g_pos[da.y], 1);
    int p2 = atomicAdd(&g_pos[da.z], 1);
    int p3 = atomicAdd(&g_pos[da.w], 1);
    int p4 = atomicAdd(&g_pos[db.x], 1);
    int p5 = atomicAdd(&g_pos[db.y], 1);
    int p6 = atomicAdd(&g_pos[db.z], 1);
    int p7 = atomicAdd(&g_pos[db.w], 1);
    g_srcs[p0] = sa.x;
    g_srcs[p1] = sa.y;
    g_srcs[p2] = sa.z;
    g_srcs[p3] = sa.w;
    g_srcs[p4] = sb.x;
    g_srcs[p5] = sb.y;
    g_srcs[p6] = sb.z;
    g_srcs[p7] = sb.w;
}

// ---------------------------------------------------------------------------
// Layer-1 gather-aggregate: z1[n] = x[n] + sum x[s] (fp32 out)
// ---------------------------------------------------------------------------
__global__ void agg1_kernel(const float* __restrict__ x) {
    int gwarp = (blockIdx.x * blockDim.x + threadIdx.x) >> 5;
    int lane = threadIdx.x & 31;
    if (gwarp >= N_NODES) return;
    int start = g_off[gwarp], end = g_off[gwarp + 1];
    float a0 = 0, a1 = 0, a2 = 0, a3 = 0, a4 = 0;
    for (int e = start + lane; e < end; e += 32) {
        int s = g_srcs[e];
        uint4 v = g_xh[s];
        float2 p0 = __half22float2(*(__half2*)&v.x);
        float2 p1 = __half22float2(*(__half2*)&v.y);
        float2 p2 = __half22float2(*(__half2*)&v.z);
        a0 += p0.x; a1 += p0.y; a2 += p1.x; a3 += p1.y; a4 += p2.x;
    }
#pragma unroll
    for (int off = 16; off; off >>= 1) {
        a0 += __shfl_xor_sync(0xffffffffu, a0, off);
        a1 += __shfl_xor_sync(0xffffffffu, a1, off);
        a2 += __shfl_xor_sync(0xffffffffu, a2, off);
        a3 += __shfl_xor_sync(0xffffffffu, a3, off);
        a4 += __shfl_xor_sync(0xffffffffu, a4, off);
    }
    if (lane == 0) {
        const float* xn = x + gwarp * 5;
        float* z = g_z1 + gwarp * 5;
        z[0] = xn[0] + a0; z[1] = xn[1] + a1; z[2] = xn[2] + a2;
        z[3] = xn[3] + a3; z[4] = xn[4] + a4;
    }
}

// ---------------------------------------------------------------------------
// MLP1 hybrid: layer-a scalar fp32 -> T1 fragments; layer-b via HMMA.
// 512 threads/block = 16 warps x 16 nodes = 256 nodes/block.
// ---------------------------------------------------------------------------
__global__ __launch_bounds__(512) void mlp1_mma_kernel(
    const float* __restrict__ W1a, const float* __restrict__ b1a,
    const float* __restrict__ W1b, const float* __restrict__ b1b) {
    __shared__ float sWa[5][HID];
    __shared__ ushort4 sWb[32][32];
    __shared__ float sba[HID];
    __shared__ float sbb[HID];
    __shared__ float sz[5][256];

    int tid = threadIdx.x;
    for (int i = tid; i < 5 * HID; i += 512) sWa[i / HID][i % HID] = W1a[i];
    for (int idx = tid; idx < 1024; idx += 512) {
        int t = idx >> 5, ln = idx & 31;
        int kt = t >> 3, nt = t & 7;
        int j = nt * 8 + (ln >> 2);
        int k0 = kt * 16 + (ln & 3) * 2;
        ushort4 wb;
        wb.x = __half_as_ushort(__float2half(W1b[(k0 + 0) * HID + j]));
        wb.y = __half_as_ushort(__float2half(W1b[(k0 + 1) * HID + j]));
        wb.z = __half_as_ushort(__float2half(W1b[(k0 + 8) * HID + j]));
        wb.w = __half_as_ushort(__float2half(W1b[(k0 + 9) * HID + j]));
        sWb[t][ln] = wb;
    }
    if (tid < HID) sba[tid] = b1a[tid];
    else if (tid < 2 * HID) sbb[tid - HID] = b1b[tid - HID];

    int base = blockIdx.x * 256;
    for (int i = tid; i < 1280; i += 512) {
        int n = i / 5, k = i % 5;
        long long gi = (long long)base * 5 + i;
        sz[k][n] = (gi < (long long)N_NODES * 5) ? g_z1[gi] : 0.0f;
    }
    __syncthreads();

    int warp = tid >> 5, lane = tid & 31;
    int n0 = base + warp * 16;
    if (n0 >= N_NODES) return;   // 100000 % 16 == 0: active tiles are full
    int r = lane >> 2;
    int cc = (lane & 3) * 2;
    int nb = warp * 16;

    float zr[5], zR[5];
#pragma unroll
    for (int k = 0; k < 5; ++k) {
        zr[k] = sz[k][nb + r];
        zR[k] = sz[k][nb + r + 8];
    }

    unsigned T1[8][2];
#pragma unroll
    for (int nt = 0; nt < 8; ++nt) {
        int j0 = nt * 8 + cc;
        float c0 = sba[j0], c1 = sba[j0 + 1];
        float c2 = c0, c3 = c1;
#pragma unroll
        for (int k = 0; k < 5; ++k) {
            float w0 = sWa[k][j0], w1 = sWa[k][j0 + 1];
            c0 += zr[k] * w0; c1 += zr[k] * w1;
            c2 += zR[k] * w0; c3 += zR[k] * w1;
        }
        __half2 p01 = __floats2half2_rn(fmaxf(c0, 0.0f), fmaxf(c1, 0.0f));
        __half2 p23 = __floats2half2_rn(fmaxf(c2, 0.0f), fmaxf(c3, 0.0f));
        T1[nt][0] = *(unsigned*)&p01;
        T1[nt][1] = *(unsigned*)&p23;
    }

    __half2* h1h = (__half2*)g_h1v;
#pragma unroll
    for (int nt = 0; nt < 8; ++nt) {
        float bias0 = sbb[nt * 8 + cc];
        float bias1 = sbb[nt * 8 + cc + 1];
        float c0 = bias0, c1 = bias1, c2 = bias0, c3 = bias1;
#pragma unroll
        for (int kt = 0; kt < 4; ++kt) {
            ushort4 w = sWb[kt * 8 + nt][lane];
            unsigned bq0 = (unsigned)w.x | ((unsigned)w.y << 16);
            unsigned bq1 = (unsigned)w.z | ((unsigned)w.w << 16);
            asm volatile(
                "mma.sync.aligned.m16n8k16.row.col.f32.f16.f16.f32 "
                "{%0,%1,%2,%3}, {%4,%5,%6,%7}, {%8,%9}, {%0,%1,%2,%3};"
                : "+f"(c0), "+f"(c1), "+f"(c2), "+f"(c3)
                : "r"(T1[2 * kt][0]), "r"(T1[2 * kt][1]),
                  "r"(T1[2 * kt + 1][0]), "r"(T1[2 * kt + 1][1]),
                  "r"(bq0), "r"(bq1));
        }
        __half2 p01 = __floats2half2_rn(fmaxf(c0, 0.0f), fmaxf(c1, 0.0f));
        __half2 p23 = __floats2half2_rn(fmaxf(c2, 0.0f), fmaxf(c3, 0.0f));
        int colh = (nt * 8 + cc) >> 1;
        h1h[(n0 + r) * (HID / 2) + colh] = p01;
        h1h[(n0 + r + 8) * (HID / 2) + colh] = p23;
    }
}

// ---------------------------------------------------------------------------
// Layer-2 gather-aggregate: 4 edges per warp-step (one LDG.128 per lane).
// ---------------------------------------------------------------------------
__global__ void agg2_kernel() {
    int gwarp = (blockIdx.x * blockDim.x + threadIdx.x) >> 5;
    int lane = threadIdx.x & 31;
    if (gwarp >= N_NODES) return;
    int start = g_off[gwarp], end = g_off[gwarp + 1];
    int sub = lane >> 3, fl = lane & 7;
    float a[8];
#pragma unroll
    for (int i = 0; i < 8; ++i) a[i] = 0.0f;

#define ACC_V(v) do { \
        float2 _p; \
        _p = __half22float2(*(__half2*)&(v).x); a[0] += _p.x; a[1] += _p.y; \
        _p = __half22float2(*(__half2*)&(v).y); a[2] += _p.x; a[3] += _p.y; \
        _p = __half22float2(*(__half2*)&(v).z); a[4] += _p.x; a[5] += _p.y; \
        _p = __half22float2(*(__half2*)&(v).w); a[6] += _p.x; a[7] += _p.y; \
    } while (0)

    int b = start;
    for (; b + 8 <= end; b += 8) {
        int s0 = g_srcs[b + sub];
        int s1 = g_srcs[b + 4 + sub];
        uint4 v0 = g_h1v[s0 * 8 + fl];
        uint4 v1 = g_h1v[s1 * 8 + fl];
        ACC_V(v0);
        ACC_V(v1);
    }
    for (; b + 4 <= end; b += 4) {
        int s0 = g_srcs[b + sub];
        uint4 v0 = g_h1v[s0 * 8 + fl];
        ACC_V(v0);
    }
    if (b + sub < end) {
        int s0 = g_srcs[b + sub];
        uint4 v0 = g_h1v[s0 * 8 + fl];
        ACC_V(v0);
    }
#undef ACC_V

#pragma unroll
    for (int off = 8; off <= 16; off <<= 1) {
#pragma unroll
        for (int i = 0; i < 8; ++i)
            a[i] += __shfl_xor_sync(0xffffffffu, a[i], off);
    }

    if (sub == 0) {
        uint4 hv = g_h1v[gwarp * 8 + fl];
        float2 p0 = __half22float2(*(__half2*)&hv.x);
        float2 p1 = __half22float2(*(__half2*)&hv.y);
        float2 p2 = __half22float2(*(__half2*)&hv.z);
        float2 p3 = __half22float2(*(__half2*)&hv.w);
        __half2 q0 = __floats2half2_rn(p0.x + a[0], p0.y + a[1]);
        __half2 q1 = __floats2half2_rn(p1.x + a[2], p1.y + a[3]);
        __half2 q2 = __floats2half2_rn(p2.x + a[4], p2.y + a[5]);
        __half2 q3 = __floats2half2_rn(p3.x + a[6], p3.y + a[7]);
        uint4 o;
        o.x = *(unsigned*)&q0; o.y = *(unsigned*)&q1;
        o.z = *(unsigned*)&q2; o.w = *(unsigned*)&q3;
        g_z2v[gwarp * 8 + fl] = o;
    }
}

// ---------------------------------------------------------------------------
// MLP2 via HMMA + warp-reduced mean-pool scatter. 512 threads/block.
// ---------------------------------------------------------------------------
__global__ __launch_bounds__(512) void mlp2_mma_kernel(
    const int* __restrict__ batch,
    const float* __restrict__ W2a, const float* __restrict__ b2a,
    const float* __restrict__ W2b, const float* __restrict__ b2b) {
    __shared__ ushort4 sWa[32][32];
    __shared__ ushort4 sWb[32][32];
    __shared__ float sba[HID];
    __shared__ float sbb[HID];

    int tid = threadIdx.x;
    for (int idx = tid; idx < 1024; idx += 512) {
        int t = idx >> 5, ln = idx & 31;
        int kt = t >> 3, nt = t & 7;
        int j = nt * 8 + (ln >> 2);
        int k0 = kt * 16 + (ln & 3) * 2;
        ushort4 wa, wb;
        wa.x = __half_as_ushort(__float2half(W2a[(k0 + 0) * HID + j]));
        wa.y = __half_as_ushort(__float2half(W2a[(k0 + 1) * HID + j]));
        wa.z = __half_as_ushort(__float2half(W2a[(k0 + 8) * HID + j]));
        wa.w = __half_as_ushort(__float2half(W2a[(k0 + 9) * HID + j]));
        wb.x = __half_as_ushort(__float2half(W2b[(k0 + 0) * HID + j]));
        wb.y = __half_as_ushort(__float2half(W2b[(k0 + 1) * HID + j]));
        wb.z = __half_as_ushort(__float2half(W2b[(k0 + 8) * HID + j]));
        wb.w = __half_as_ushort(__float2half(W2b[(k0 + 9) * HID + j]));
        sWa[t][ln] = wa;
        sWb[t][ln] = wb;
    }
    if (tid < HID) sba[tid] = b2a[tid];
    else if (tid < 2 * HID) sbb[tid - HID] = b2b[tid - HID];
    __syncthreads();

    int warp = tid >> 5, lane = tid & 31;
    int wt = blockIdx.x * 16 + warp;
    if (wt >= WARP_TILES) return;
    int n0 = wt * 16;
    int r = lane >> 2;
    int cc = (lane & 3) * 2;

    const __half* z2h = (const __half*)g_z2v;
    unsigned A[4][4];
#pragma unroll
    for (int kt = 0; kt < 4; ++kt) {
        int col = kt * 16 + cc;
        A[kt][0] = *(const unsigned*)&z2h[(n0 + r) * HID + col];
        A[kt][1] = *(const unsigned*)&z2h[(n0 + r + 8) * HID + col];
        A[kt][2] = *(const unsigned*)&z2h[(n0 + r) * HID + col + 8];
        A[kt][3] = *(const unsigned*)&z2h[(n0 + r + 8) * HID + col + 8];
    }

    unsigned T1[8][2];
#pragma unroll
    for (int nt = 0; nt < 8; ++nt) {
        float bias0 = sba[nt * 8 + cc];
        float bias1 = sba[nt * 8 + cc + 1];
        float c0 = bias0, c1 = bias1, c2 = bias0, c3 = bias1;
#pragma unroll
        for (int kt = 0; kt < 4; ++kt) {
            ushort4 w = sWa[kt * 8 + nt][lane];
            unsigned bq0 = (unsigned)w.x | ((unsigned)w.y << 16);
            unsigned bq1 = (unsigned)w.z | ((unsigned)w.w << 16);
            asm volatile(
                "mma.sync.aligned.m16n8k16.row.col.f32.f16.f16.f32 "
                "{%0,%1,%2,%3}, {%4,%5,%6,%7}, {%8,%9}, {%0,%1,%2,%3};"
                : "+f"(c0), "+f"(c1), "+f"(c2), "+f"(c3)
                : "r"(A[kt][0]), "r"(A[kt][1]), "r"(A[kt][2]), "r"(A[kt][3]),
                  "r"(bq0), "r"(bq1));
        }
        __half2 p01 = __floats2half2_rn(fmaxf(c0, 0.0f), fmaxf(c1, 0.0f));
        __half2 p23 = __floats2half2_rn(fmaxf(c2, 0.0f), fmaxf(c3, 0.0f));
        T1[nt][0] = *(unsigned*)&p01;
        T1[nt][1] = *(unsigned*)&p23;
    }

    int gA = batch[n0 + r];
    int gB = batch[n0 + r + 8];
    int gf = __shfl_sync(0xffffffffu, gA, 0);
    bool uniform = __all_sync(0xffffffffu, (gA == gf) && (gB == gf));

#pragma unroll
    for (int nt = 0; nt < 8; ++nt) {
        float bias0 = sbb[nt * 8 + cc];
        float bias1 = sbb[nt * 8 + cc + 1];
        float c0 = bias0, c1 = bias1, c2 = bias0, c3 = bias1;
#pragma unroll
        for (int kt = 0; kt < 4; ++kt) {
            ushort4 w = sWb[kt * 8 + nt][lane];
            unsigned bq0 = (unsigned)w.x | ((unsigned)w.y << 16);
            unsigned bq1 = (unsigned)w.z | ((unsigned)w.w << 16);
            asm volatile(
                "mma.sync.aligned.m16n8k16.row.col.f32.f16.f16.f32 "
                "{%0,%1,%2,%3}, {%4,%5,%6,%7}, {%8,%9}, {%0,%1,%2,%3};"
                : "+f"(c0), "+f"(c1), "+f"(c2), "+f"(c3)
                : "r"(T1[2 * kt][0]), "r"(T1[2 * kt][1]),
                  "r"(T1[2 * kt + 1][0]), "r"(T1[2 * kt + 1][1]),
                  "r"(bq0), "r"(bq1));
        }
        int col = nt * 8 + cc;
        float v0 = fmaxf(c0, 0.0f), v1 = fmaxf(c1, 0.0f);
        float v2 = fmaxf(c2, 0.0f), v3 = fmaxf(c3, 0.0f);
        if (uniform) {
            float s0 = v0 + v2, s1 = v1 + v3;
#pragma unroll
            for (int off = 4; off <= 16; off <<= 1) {
                s0 += __shfl_xor_sync(0xffffffffu, s0, off);
                s1 += __shfl_xor_sync(0xffffffffu, s1, off);
            }
            if (lane < 4) {
                atomicAdd(&g_gsum[gf * HID + col],     s0);
                atomicAdd(&g_gsum[gf * HID + col + 1], s1);
            }
        } else {
            atomicAdd(&g_gsum[gA * HID + col],     v0);
            atomicAdd(&g_gsum[gA * HID + col + 1], v1);
            atomicAdd(&g_gsum[gB * HID + col],     v2);
            atomicAdd(&g_gsum[gB * HID + col + 1], v3);
        }
    }
}

// ---------------------------------------------------------------------------
// Head (fused graph-size via binary search on sorted batch). After reading
// its own gsum row, each thread re-zeros it (restores the launch invariant).
// ---------------------------------------------------------------------------
__device__ __forceinline__ int lower_bound_batch(const int* b, int key) {
    int lo = 0, hi = N_NODES;
    while (lo < hi) {
        int mid = (lo + hi) >> 1;
        if (b[mid] < key) lo = mid + 1; else hi = mid;
    }
    return lo;
}
__global__ void head_kernel(const int* __restrict__ batch,
                            const float* __restrict__ Wc,
                            const float* __restrict__ bc,
                            float* __restrict__ out) {
    int g = blockIdx.x * blockDim.x + threadIdx.x;
    if (g >= N_GRAPHS) return;
    int a = lower_bound_batch(batch, g);
    int b = lower_bound_batch(batch, g + 1);
    float inv = 1.0f / fmaxf((float)(b - a), 1.0f);
    float a0 = bc[0], a1 = bc[1];
#pragma unroll
    for (int jj = 0; jj < HID; ++jj) {
        float p = g_gsum[g * HID + jj] * inv;
        a0 += p * Wc[jj * 2 + 0];
        a1 += p * Wc[jj * 2 + 1];
    }
    out[g * 2 + 0] = a0;
    out[g * 2 + 1] = a1;
    // restore zero invariant for this graph's row (only this thread reads it)
#pragma unroll
    for (int jj = 0; jj < HID; ++jj) g_gsum[g * HID + jj] = 0.0f;
}

// ---------------------------------------------------------------------------
extern "C" void kernel_launch(void* const* d_in, const int* in_sizes, int n_in,
                              void* d_out, int out_size) {
    const float* x   = (const float*)d_in[0];
    const int*   ei  = (const int*)d_in[1];
    const int*   bat = (const int*)d_in[2];
    const float* W1a = (const float*)d_in[3];
    const float* b1a = (const float*)d_in[4];
    const float* W1b = (const float*)d_in[5];
    const float* b1b = (const float*)d_in[6];
    const float* W2a = (const float*)d_in[7];
    const float* b2a = (const float*)d_in[8];
    const float* W2b = (const float*)d_in[9];
    const float* b2b = (const float*)d_in[10];
    const float* Wc  = (const float*)d_in[11];
    const float* bc  = (const float*)d_in[12];
    float* out = (float*)d_out;

    prep_hist_kernel<<<(N_EDGES / 8 + 255) / 256, 256>>>(x, ei);
    scanA_kernel<<<SCAN_BLOCKS, 256>>>();
    scanC_kernel<<<SCAN_BLOCKS, 256>>>();
    scatter_kernel<<<(N_EDGES / 8 + 255) / 256, 256>>>(ei);

    // layer 1
    agg1_kernel<<<(N_NODES * 32 + 255) / 256, 256>>>(x);
    mlp1_mma_kernel<<<(N_NODES + 255) / 256, 512>>>(W1a, b1a, W1b, b1b);

    // layer 2
    agg2_kernel<<<(N_NODES * 32 + 255) / 256, 256>>>();
    mlp2_mma_kernel<<<(WARP_TILES + 15) / 16, 512>>>(bat, W2a, b2a, W2b, b2b);

    head_kernel<<<(N_GRAPHS + 255) / 256, 256>>>(bat, Wc, bc, out);
}

// round 16
// speedup vs baseline: 1.0642x; 1.0642x over previous
#include <cuda_runtime.h>
#include <cuda_fp16.h>
#include <cstdint>

#define N_NODES 100000
#define N_EDGES 3200000
#define N_GRAPHS 1024
#define HID 64

#define SCAN_BLOCKS 98   // ceil(100000 / 1024)
#define WARP_TILES 6250  // 100000 / 16 (exact)

// ---------------------------------------------------------------------------
// Scratch (device globals; no allocations allowed)
// ---------------------------------------------------------------------------
__device__ int     g_deg[N_NODES + 4];
__device__ int     g_off[N_NODES + 1];
__device__ int     g_rank[N_EDGES];          // per-edge rank within dst bucket
__device__ int     g_srcs[N_EDGES];
__device__ int     g_bsum[SCAN_BLOCKS];
__device__ uint4   g_xh[N_NODES];            // x padded to 8 halfs
__device__ float   g_z1[N_NODES * 5 + 12];
__device__ uint4   g_h1v[N_NODES * 8];       // layer-1 output, fp16 [N][64]
__device__ uint4   g_z2v[N_NODES * 8];       // h1 + agg2, fp16 [N][64]
__device__ float   g_gsum[N_GRAPHS * HID];

// ---------------------------------------------------------------------------
// Pack x into fp16 rows + zero deg/gsum. Grid covers N_NODES+4 threads.
// ---------------------------------------------------------------------------
__global__ void prep_kernel(const float* __restrict__ x) {
    int n = blockIdx.x * blockDim.x + threadIdx.x;
    if (n < N_NODES) {
        const float* xs = x + n * 5;
        __half2 h0 = __floats2half2_rn(xs[0], xs[1]);
        __half2 h1 = __floats2half2_rn(xs[2], xs[3]);
        __half2 h2 = __floats2half2_rn(xs[4], 0.0f);
        __half2 h3 = __floats2half2_rn(0.0f, 0.0f);
        uint4 v;
        v.x = *(unsigned*)&h0; v.y = *(unsigned*)&h1;
        v.z = *(unsigned*)&h2; v.w = *(unsigned*)&h3;
        g_xh[n] = v;
    }
    if (n < N_NODES + 4) g_deg[n] = 0;
    if (n < N_GRAPHS * HID) g_gsum[n] = 0.0f;
}

// ---------------------------------------------------------------------------
// Degree histogram with rank capture, 8 edges/thread.
// ---------------------------------------------------------------------------
__global__ void hist_kernel(const int* __restrict__ ei) {
    int t = blockIdx.x * blockDim.x + threadIdx.x;
    if (t >= N_EDGES / 8) return;
    const int4* dp = (const int4*)(ei + N_EDGES);
    int4 a = dp[2 * t], b = dp[2 * t + 1];
    int4 ra, rb;
    ra.x = atomicAdd(&g_deg[a.x], 1);
    ra.y = atomicAdd(&g_deg[a.y], 1);
    ra.z = atomicAdd(&g_deg[a.z], 1);
    ra.w = atomicAdd(&g_deg[a.w], 1);
    rb.x = atomicAdd(&g_deg[b.x], 1);
    rb.y = atomicAdd(&g_deg[b.y], 1);
    rb.z = atomicAdd(&g_deg[b.z], 1);
    rb.w = atomicAdd(&g_deg[b.w], 1);
    ((int4*)g_rank)[2 * t] = ra;
    ((int4*)g_rank)[2 * t + 1] = rb;
}

// ---------------------------------------------------------------------------
// Scan phase A: per-block sums (1024 nodes/block).
// ---------------------------------------------------------------------------
__global__ void scanA_kernel() {
    __shared__ int wsum[8];
    int t = threadIdx.x;
    int n0 = blockIdx.x * 1024 + t * 4;
    int s = 0;
    if (n0 + 3 < N_NODES) {
        int4 v = *(const int4*)&g_deg[n0];
        s = v.x + v.y + v.z + v.w;
    } else {
#pragma unroll
        for (int i = 0; i < 4; ++i)
            if (n0 + i < N_NODES) s += g_deg[n0 + i];
    }
    int lane = t & 31;
#pragma unroll
    for (int off = 16; off; off >>= 1) s += __shfl_xor_sync(0xffffffffu, s, off);
    if (lane == 0) wsum[t >> 5] = s;
    __syncthreads();
    if (t < 8) {
        int v = wsum[t];
#pragma unroll
        for (int off = 4; off; off >>= 1) v += __shfl_xor_sync(0xffu, v, off);
        if (t == 0) g_bsum[blockIdx.x] = v;
    }
}

// ---------------------------------------------------------------------------
// Scan phase C (with inlined phase B); writes g_off.
// ---------------------------------------------------------------------------
__global__ void scanC_kernel() {
    __shared__ int sbs[128];
    __shared__ int ssum[256];
    int t = threadIdx.x;
    if (t < 128) sbs[t] = (t < SCAN_BLOCKS) ? g_bsum[t] : 0;
    __syncthreads();
    for (int d = 1; d < 128; d <<= 1) {
        int u = (t >= d && t < 128) ? sbs[t - d] : 0;
        __syncthreads();
        if (t < 128) sbs[t] += u;
        __syncthreads();
    }
    int boff = (blockIdx.x == 0) ? 0 : sbs[blockIdx.x - 1];
    if (blockIdx.x == 0 && t == 0) g_off[N_NODES] = sbs[SCAN_BLOCKS - 1];

    int n0 = blockIdx.x * 1024 + t * 4;
    int v0 = 0, v1 = 0, v2 = 0, v3 = 0;
    if (n0 + 3 < N_NODES) {
        int4 v = *(const int4*)&g_deg[n0];
        v0 = v.x; v1 = v.y; v2 = v.z; v3 = v.w;
    } else {
        if (n0 + 0 < N_NODES) v0 = g_deg[n0 + 0];
        if (n0 + 1 < N_NODES) v1 = g_deg[n0 + 1];
        if (n0 + 2 < N_NODES) v2 = g_deg[n0 + 2];
        if (n0 + 3 < N_NODES) v3 = g_deg[n0 + 3];
    }
    int s = v0 + v1 + v2 + v3;
    ssum[t] = s;
    __syncthreads();
    for (int d = 1; d < 256; d <<= 1) {
        int u = (t >= d) ? ssum[t - d] : 0;
        __syncthreads();
        ssum[t] += u;
        __syncthreads();
    }
    int prefix = boff + ssum[t] - s;
    if (n0 + 0 < N_NODES) { g_off[n0 + 0] = prefix; prefix += v0; }
    if (n0 + 1 < N_NODES) { g_off[n0 + 1] = prefix; prefix += v1; }
    if (n0 + 2 < N_NODES) { g_off[n0 + 2] = prefix; prefix += v2; }
    if (n0 + 3 < N_NODES) { g_off[n0 + 3] = prefix; }
}

// ---------------------------------------------------------------------------
// Scatter edges into CSR (no atomics: rank precomputed), 8 edges/thread.
// ---------------------------------------------------------------------------
__global__ void scatter_kernel(const int* __restrict__ ei) {
    int t = blockIdx.x * blockDim.x + threadIdx.x;
    if (t >= N_EDGES / 8) return;
    const int4* sp = (const int4*)ei;
    const int4* dp = (const int4*)(ei + N_EDGES);
    const int4* rp = (const int4*)g_rank;
    int4 sa = sp[2 * t], sb = sp[2 * t + 1];
    int4 da = dp[2 * t], db = dp[2 * t + 1];
    int4 ra = rp[2 * t], rb = rp[2 * t + 1];
    g_srcs[__ldg(&g_off[da.x]) + ra.x] = sa.x;
    g_srcs[__ldg(&g_off[da.y]) + ra.y] = sa.y;
    g_srcs[__ldg(&g_off[da.z]) + ra.z] = sa.z;
    g_srcs[__ldg(&g_off[da.w]) + ra.w] = sa.w;
    g_srcs[__ldg(&g_off[db.x]) + rb.x] = sb.x;
    g_srcs[__ldg(&g_off[db.y]) + rb.y] = sb.y;
    g_srcs[__ldg(&g_off[db.z]) + rb.z] = sb.z;
    g_srcs[__ldg(&g_off[db.w]) + rb.w] = sb.w;
}

// ---------------------------------------------------------------------------
// Layer-1 gather-aggregate: z1[n] = x[n] + sum x[s] (fp32 out)
// ---------------------------------------------------------------------------
__global__ void agg1_kernel(const float* __restrict__ x) {
    int gwarp = (blockIdx.x * blockDim.x + threadIdx.x) >> 5;
    int lane = threadIdx.x & 31;
    if (gwarp >= N_NODES) return;
    int start = g_off[gwarp], end = g_off[gwarp + 1];
    float a0 = 0, a1 = 0, a2 = 0, a3 = 0, a4 = 0;
    for (int e = start + lane; e < end; e += 32) {
        int s = g_srcs[e];
        uint4 v = g_xh[s];
        float2 p0 = __half22float2(*(__half2*)&v.x);
        float2 p1 = __half22float2(*(__half2*)&v.y);
        float2 p2 = __half22float2(*(__half2*)&v.z);
        a0 += p0.x; a1 += p0.y; a2 += p1.x; a3 += p1.y; a4 += p2.x;
    }
#pragma unroll
    for (int off = 16; off; off >>= 1) {
        a0 += __shfl_xor_sync(0xffffffffu, a0, off);
        a1 += __shfl_xor_sync(0xffffffffu, a1, off);
        a2 += __shfl_xor_sync(0xffffffffu, a2, off);
        a3 += __shfl_xor_sync(0xffffffffu, a3, off);
        a4 += __shfl_xor_sync(0xffffffffu, a4, off);
    }
    if (lane == 0) {
        const float* xn = x + gwarp * 5;
        float* z = g_z1 + gwarp * 5;
        z[0] = xn[0] + a0; z[1] = xn[1] + a1; z[2] = xn[2] + a2;
        z[3] = xn[3] + a3; z[4] = xn[4] + a4;
    }
}

// ---------------------------------------------------------------------------
// MLP1 hybrid: layer-a scalar fp32 -> T1 fragments; layer-b via HMMA.
// 256 threads/block (R14 config).
// ---------------------------------------------------------------------------
__global__ __launch_bounds__(256) void mlp1_mma_kernel(
    const float* __restrict__ W1a, const float* __restrict__ b1a,
    const float* __restrict__ W1b, const float* __restrict__ b1b) {
    __shared__ float sWa[5][HID];
    __shared__ ushort4 sWb[32][32];
    __shared__ float sba[HID];
    __shared__ float sbb[HID];
    __shared__ float sz[5][128];

    int tid = threadIdx.x;
    for (int i = tid; i < 5 * HID; i += 256) sWa[i / HID][i % HID] = W1a[i];
    for (int idx = tid; idx < 1024; idx += 256) {
        int t = idx >> 5, ln = idx & 31;
        int kt = t >> 3, nt = t & 7;
        int j = nt * 8 + (ln >> 2);
        int k0 = kt * 16 + (ln & 3) * 2;
        ushort4 wb;
        wb.x = __half_as_ushort(__float2half(W1b[(k0 + 0) * HID + j]));
        wb.y = __half_as_ushort(__float2half(W1b[(k0 + 1) * HID + j]));
        wb.z = __half_as_ushort(__float2half(W1b[(k0 + 8) * HID + j]));
        wb.w = __half_as_ushort(__float2half(W1b[(k0 + 9) * HID + j]));
        sWb[t][ln] = wb;
    }
    if (tid < HID) sba[tid] = b1a[tid];
    else if (tid < 2 * HID) sbb[tid - HID] = b1b[tid - HID];

    int base = blockIdx.x * 128;
    for (int i = tid; i < 640; i += 256) {
        int n = i / 5, k = i % 5;
        long long gi = (long long)base * 5 + i;
        sz[k][n] = (gi < (long long)N_NODES * 5) ? g_z1[gi] : 0.0f;
    }
    __syncthreads();

    int warp = tid >> 5, lane = tid & 31;
    int n0 = base + warp * 16;
    if (n0 >= N_NODES) return;
    int r = lane >> 2;
    int cc = (lane & 3) * 2;
    int nb = warp * 16;

    float zr[5], zR[5];
#pragma unroll
    for (int k = 0; k < 5; ++k) {
        zr[k] = sz[k][nb + r];
        zR[k] = sz[k][nb + r + 8];
    }

    unsigned T1[8][2];
#pragma unroll
    for (int nt = 0; nt < 8; ++nt) {
        int j0 = nt * 8 + cc;
        float c0 = sba[j0], c1 = sba[j0 + 1];
        float c2 = c0, c3 = c1;
#pragma unroll
        for (int k = 0; k < 5; ++k) {
            float w0 = sWa[k][j0], w1 = sWa[k][j0 + 1];
            c0 += zr[k] * w0; c1 += zr[k] * w1;
            c2 += zR[k] * w0; c3 += zR[k] * w1;
        }
        __half2 p01 = __floats2half2_rn(fmaxf(c0, 0.0f), fmaxf(c1, 0.0f));
        __half2 p23 = __floats2half2_rn(fmaxf(c2, 0.0f), fmaxf(c3, 0.0f));
        T1[nt][0] = *(unsigned*)&p01;
        T1[nt][1] = *(unsigned*)&p23;
    }

    __half2* h1h = (__half2*)g_h1v;
#pragma unroll
    for (int nt = 0; nt < 8; ++nt) {
        float bias0 = sbb[nt * 8 + cc];
        float bias1 = sbb[nt * 8 + cc + 1];
        float c0 = bias0, c1 = bias1, c2 = bias0, c3 = bias1;
#pragma unroll
        for (int kt = 0; kt < 4; ++kt) {
            ushort4 w = sWb[kt * 8 + nt][lane];
            unsigned bq0 = (unsigned)w.x | ((unsigned)w.y << 16);
            unsigned bq1 = (unsigned)w.z | ((unsigned)w.w << 16);
            asm volatile(
                "mma.sync.aligned.m16n8k16.row.col.f32.f16.f16.f32 "
                "{%0,%1,%2,%3}, {%4,%5,%6,%7}, {%8,%9}, {%0,%1,%2,%3};"
                : "+f"(c0), "+f"(c1), "+f"(c2), "+f"(c3)
                : "r"(T1[2 * kt][0]), "r"(T1[2 * kt][1]),
                  "r"(T1[2 * kt + 1][0]), "r"(T1[2 * kt + 1][1]),
                  "r"(bq0), "r"(bq1));
        }
        __half2 p01 = __floats2half2_rn(fmaxf(c0, 0.0f), fmaxf(c1, 0.0f));
        __half2 p23 = __floats2half2_rn(fmaxf(c2, 0.0f), fmaxf(c3, 0.0f));
        int colh = (nt * 8 + cc) >> 1;
        h1h[(n0 + r) * (HID / 2) + colh] = p01;
        h1h[(n0 + r + 8) * (HID / 2) + colh] = p23;
    }
}

// ---------------------------------------------------------------------------
// Layer-2 gather-aggregate: 4 edges per warp-step (one LDG.128 per lane).
// ---------------------------------------------------------------------------
__global__ void agg2_kernel() {
    int gwarp = (blockIdx.x * blockDim.x + threadIdx.x) >> 5;
    int lane = threadIdx.x & 31;
    if (gwarp >= N_NODES) return;
    int start = g_off[gwarp], end = g_off[gwarp + 1];
    int sub = lane >> 3, fl = lane & 7;
    float a[8];
#pragma unroll
    for (int i = 0; i < 8; ++i) a[i] = 0.0f;

#define ACC_V(v) do { \
        float2 _p; \
        _p = __half22float2(*(__half2*)&(v).x); a[0] += _p.x; a[1] += _p.y; \
        _p = __half22float2(*(__half2*)&(v).y); a[2] += _p.x; a[3] += _p.y; \
        _p = __half22float2(*(__half2*)&(v).z); a[4] += _p.x; a[5] += _p.y; \
        _p = __half22float2(*(__half2*)&(v).w); a[6] += _p.x; a[7] += _p.y; \
    } while (0)

    int b = start;
    for (; b + 8 <= end; b += 8) {
        int s0 = g_srcs[b + sub];
        int s1 = g_srcs[b + 4 + sub];
        uint4 v0 = g_h1v[s0 * 8 + fl];
        uint4 v1 = g_h1v[s1 * 8 + fl];
        ACC_V(v0);
        ACC_V(v1);
    }
    for (; b + 4 <= end; b += 4) {
        int s0 = g_srcs[b + sub];
        uint4 v0 = g_h1v[s0 * 8 + fl];
        ACC_V(v0);
    }
    if (b + sub < end) {
        int s0 = g_srcs[b + sub];
        uint4 v0 = g_h1v[s0 * 8 + fl];
        ACC_V(v0);
    }
#undef ACC_V

#pragma unroll
    for (int off = 8; off <= 16; off <<= 1) {
#pragma unroll
        for (int i = 0; i < 8; ++i)
            a[i] += __shfl_xor_sync(0xffffffffu, a[i], off);
    }

    if (sub == 0) {
        uint4 hv = g_h1v[gwarp * 8 + fl];
        float2 p0 = __half22float2(*(__half2*)&hv.x);
        float2 p1 = __half22float2(*(__half2*)&hv.y);
        float2 p2 = __half22float2(*(__half2*)&hv.z);
        float2 p3 = __half22float2(*(__half2*)&hv.w);
        __half2 q0 = __floats2half2_rn(p0.x + a[0], p0.y + a[1]);
        __half2 q1 = __floats2half2_rn(p1.x + a[2], p1.y + a[3]);
        __half2 q2 = __floats2half2_rn(p2.x + a[4], p2.y + a[5]);
        __half2 q3 = __floats2half2_rn(p3.x + a[6], p3.y + a[7]);
        uint4 o;
        o.x = *(unsigned*)&q0; o.y = *(unsigned*)&q1;
        o.z = *(unsigned*)&q2; o.w = *(unsigned*)&q3;
        g_z2v[gwarp * 8 + fl] = o;
    }
}

// ---------------------------------------------------------------------------
// MLP2 via HMMA + warp-reduced mean-pool scatter. 512 threads/block.
// ---------------------------------------------------------------------------
__global__ __launch_bounds__(512) void mlp2_mma_kernel(
    const int* __restrict__ batch,
    const float* __restrict__ W2a, const float* __restrict__ b2a,
    const float* __restrict__ W2b, const float* __restrict__ b2b) {
    __shared__ ushort4 sWa[32][32];
    __shared__ ushort4 sWb[32][32];
    __shared__ float sba[HID];
    __shared__ float sbb[HID];

    int tid = threadIdx.x;
    for (int idx = tid; idx < 1024; idx += 512) {
        int t = idx >> 5, ln = idx & 31;
        int kt = t >> 3, nt = t & 7;
        int j = nt * 8 + (ln >> 2);
        int k0 = kt * 16 + (ln & 3) * 2;
        ushort4 wa, wb;
        wa.x = __half_as_ushort(__float2half(W2a[(k0 + 0) * HID + j]));
        wa.y = __half_as_ushort(__float2half(W2a[(k0 + 1) * HID + j]));
        wa.z = __half_as_ushort(__float2half(W2a[(k0 + 8) * HID + j]));
        wa.w = __half_as_ushort(__float2half(W2a[(k0 + 9) * HID + j]));
        wb.x = __half_as_ushort(__float2half(W2b[(k0 + 0) * HID + j]));
        wb.y = __half_as_ushort(__float2half(W2b[(k0 + 1) * HID + j]));
        wb.z = __half_as_ushort(__float2half(W2b[(k0 + 8) * HID + j]));
        wb.w = __half_as_ushort(__float2half(W2b[(k0 + 9) * HID + j]));
        sWa[t][ln] = wa;
        sWb[t][ln] = wb;
    }
    if (tid < HID) sba[tid] = b2a[tid];
    else if (tid < 2 * HID) sbb[tid - HID] = b2b[tid - HID];
    __syncthreads();

    int warp = tid >> 5, lane = tid & 31;
    int wt = blockIdx.x * 16 + warp;
    if (wt >= WARP_TILES) return;
    int n0 = wt * 16;
    int r = lane >> 2;
    int cc = (lane & 3) * 2;

    const __half* z2h = (const __half*)g_z2v;
    unsigned A[4][4];
#pragma unroll
    for (int kt = 0; kt < 4; ++kt) {
        int col = kt * 16 + cc;
        A[kt][0] = *(const unsigned*)&z2h[(n0 + r) * HID + col];
        A[kt][1] = *(const unsigned*)&z2h[(n0 + r + 8) * HID + col];
        A[kt][2] = *(const unsigned*)&z2h[(n0 + r) * HID + col + 8];
        A[kt][3] = *(const unsigned*)&z2h[(n0 + r + 8) * HID + col + 8];
    }

    unsigned T1[8][2];
#pragma unroll
    for (int nt = 0; nt < 8; ++nt) {
        float bias0 = sba[nt * 8 + cc];
        float bias1 = sba[nt * 8 + cc + 1];
        float c0 = bias0, c1 = bias1, c2 = bias0, c3 = bias1;
#pragma unroll
        for (int kt = 0; kt < 4; ++kt) {
            ushort4 w = sWa[kt * 8 + nt][lane];
            unsigned bq0 = (unsigned)w.x | ((unsigned)w.y << 16);
            unsigned bq1 = (unsigned)w.z | ((unsigned)w.w << 16);
            asm volatile(
                "mma.sync.aligned.m16n8k16.row.col.f32.f16.f16.f32 "
                "{%0,%1,%2,%3}, {%4,%5,%6,%7}, {%8,%9}, {%0,%1,%2,%3};"
                : "+f"(c0), "+f"(c1), "+f"(c2), "+f"(c3)
                : "r"(A[kt][0]), "r"(A[kt][1]), "r"(A[kt][2]), "r"(A[kt][3]),
                  "r"(bq0), "r"(bq1));
        }
        __half2 p01 = __floats2half2_rn(fmaxf(c0, 0.0f), fmaxf(c1, 0.0f));
        __half2 p23 = __floats2half2_rn(fmaxf(c2, 0.0f), fmaxf(c3, 0.0f));
        T1[nt][0] = *(unsigned*)&p01;
        T1[nt][1] = *(unsigned*)&p23;
    }

    int gA = batch[n0 + r];
    int gB = batch[n0 + r + 8];
    int gf = __shfl_sync(0xffffffffu, gA, 0);
    bool uniform = __all_sync(0xffffffffu, (gA == gf) && (gB == gf));

#pragma unroll
    for (int nt = 0; nt < 8; ++nt) {
        float bias0 = sbb[nt * 8 + cc];
        float bias1 = sbb[nt * 8 + cc + 1];
        float c0 = bias0, c1 = bias1, c2 = bias0, c3 = bias1;
#pragma unroll
        for (int kt = 0; kt < 4; ++kt) {
            ushort4 w = sWb[kt * 8 + nt][lane];
            unsigned bq0 = (unsigned)w.x | ((unsigned)w.y << 16);
            unsigned bq1 = (unsigned)w.z | ((unsigned)w.w << 16);
            asm volatile(
                "mma.sync.aligned.m16n8k16.row.col.f32.f16.f16.f32 "
                "{%0,%1,%2,%3}, {%4,%5,%6,%7}, {%8,%9}, {%0,%1,%2,%3};"
                : "+f"(c0), "+f"(c1), "+f"(c2), "+f"(c3)
                : "r"(T1[2 * kt][0]), "r"(T1[2 * kt][1]),
                  "r"(T1[2 * kt + 1][0]), "r"(T1[2 * kt + 1][1]),
                  "r"(bq0), "r"(bq1));
        }
        int col = nt * 8 + cc;
        float v0 = fmaxf(c0, 0.0f), v1 = fmaxf(c1, 0.0f);
        float v2 = fmaxf(c2, 0.0f), v3 = fmaxf(c3, 0.0f);
        if (uniform) {
            float s0 = v0 + v2, s1 = v1 + v3;
#pragma unroll
            for (int off = 4; off <= 16; off <<= 1) {
                s0 += __shfl_xor_sync(0xffffffffu, s0, off);
                s1 += __shfl_xor_sync(0xffffffffu, s1, off);
            }
            if (lane < 4) {
                atomicAdd(&g_gsum[gf * HID + col],     s0);
                atomicAdd(&g_gsum[gf * HID + col + 1], s1);
            }
        } else {
            atomicAdd(&g_gsum[gA * HID + col],     v0);
            atomicAdd(&g_gsum[gA * HID + col + 1], v1);
            atomicAdd(&g_gsum[gB * HID + col],     v2);
            atomicAdd(&g_gsum[gB * HID + col + 1], v3);
        }
    }
}

// ---------------------------------------------------------------------------
// Head (fused graph-size via binary search on sorted batch).
// ---------------------------------------------------------------------------
__device__ __forceinline__ int lower_bound_batch(const int* b, int key) {
    int lo = 0, hi = N_NODES;
    while (lo < hi) {
        int mid = (lo + hi) >> 1;
        if (b[mid] < key) lo = mid + 1; else hi = mid;
    }
    return lo;
}
__global__ void head_kernel(const int* __restrict__ batch,
                            const float* __restrict__ Wc,
                            const float* __restrict__ bc,
                            float* __restrict__ out) {
    int g = blockIdx.x * blockDim.x + threadIdx.x;
    if (g >= N_GRAPHS) return;
    int a = lower_bound_batch(batch, g);
    int b = lower_bound_batch(batch, g + 1);
    float inv = 1.0f / fmaxf((float)(b - a), 1.0f);
    float a0 = bc[0], a1 = bc[1];
#pragma unroll
    for (int jj = 0; jj < HID; ++jj) {
        float p = g_gsum[g * HID + jj] * inv;
        a0 += p * Wc[jj * 2 + 0];
        a1 += p * Wc[jj * 2 + 1];
    }
    out[g * 2 + 0] = a0;
    out[g * 2 + 1] = a1;
}

// ---------------------------------------------------------------------------
extern "C" void kernel_launch(void* const* d_in, const int* in_sizes, int n_in,
                              void* d_out, int out_size) {
    const float* x   = (const float*)d_in[0];
    const int*   ei  = (const int*)d_in[1];
    const int*   bat = (const int*)d_in[2];
    const float* W1a = (const float*)d_in[3];
    const float* b1a = (const float*)d_in[4];
    const float* W1b = (const float*)d_in[5];
    const float* b1b = (const float*)d_in[6];
    const float* W2a = (const float*)d_in[7];
    const float* b2a = (const float*)d_in[8];
    const float* W2b = (const float*)d_in[9];
    const float* b2b = (const float*)d_in[10];
    const float* Wc  = (const float*)d_in[11];
    const float* bc  = (const float*)d_in[12];
    float* out = (float*)d_out;

    prep_kernel<<<(N_NODES + 4 + 255) / 256, 256>>>(x);
    hist_kernel<<<(N_EDGES / 8 + 255) / 256, 256>>>(ei);
    scanA_kernel<<<SCAN_BLOCKS, 256>>>();
    scanC_kernel<<<SCAN_BLOCKS, 256>>>();
    scatter_kernel<<<(N_EDGES / 8 + 255) / 256, 256>>>(ei);

    // layer 1
    agg1_kernel<<<(N_NODES * 32 + 255) / 256, 256>>>(x);
    mlp1_mma_kernel<<<(N_NODES + 127) / 128, 256>>>(W1a, b1a, W1b, b1b);

    // layer 2
    agg2_kernel<<<(N_NODES * 32 + 255) / 256, 256>>>();
    mlp2_mma_kernel<<<(WARP_TILES + 15) / 16, 512>>>(bat, W2a, b2a, W2b, b2b);

    head_kernel<<<(N_GRAPHS + 255) / 256, 256>>>(bat, Wc, bc, out);
}